// round 5
// baseline (speedup 1.0000x reference)
#include <cuda_runtime.h>

#define DEV_INLINE __device__ __forceinline__

constexpr int cN   = 100000;   // nodes
constexpr int cE   = 1600000;  // edges
constexpr int cDIN = 32;       // node in channels
constexpr int cDE  = 16;       // edge feature dim
constexpr int cH   = 64;       // hidden
constexpr int cMH  = 128;      // mlp hidden
constexpr int cOUT = 10;       // out channels
constexpr int cG   = 128;      // graphs

typedef unsigned long long ull;

// ---------------- scratch (device globals; no allocation allowed) ----------
__device__ __align__(16) float g_u[cN * cH];       // x + agg (node MLP input)
__device__ __align__(16) float g_h[cN * cH];       // node MLP output (pre-BN)
__device__ __align__(16) float g_x[cN * cH];       // post-BN activations
__device__ __align__(16) float g_ea_perm[(size_t)cE * cDE];  // ea in CSR order
__device__ __align__(16) int   g_src[cE];          // src in CSR order
__device__ __align__(16) int   g_deg[cN];          // zeroed by scan (self-restoring)
__device__ __align__(16) int   g_woff[cN];
__device__ __align__(16) int   g_rowptr[cN + 1];
__device__ __align__(16) float g_sum[cH];
__device__ __align__(16) float g_sumsq[cH];
__device__ __align__(16) float g_pool[cG * cH];
__device__ __align__(16) int   g_cnt[cG];

DEV_INLINE void red_add_v4(float* p, float a, float b, float c, float d) {
    asm volatile("red.global.add.v4.f32 [%0], {%1,%2,%3,%4};"
                 :: "l"(p), "f"(a), "f"(b), "f"(c), "f"(d) : "memory");
}
DEV_INLINE ull ffma2(ull a, ull b, ull c) {
    ull d;
    asm("fma.rn.f32x2 %0, %1, %2, %3;" : "=l"(d) : "l"(a), "l"(b), "l"(c));
    return d;
}
DEV_INLINE ull pack2(float lo, float hi) {
    ull v;
    asm("mov.b64 %0, {%1, %2};" : "=l"(v) : "f"(lo), "f"(hi));
    return v;
}
DEV_INLINE float2 unpack2(ull v) {
    float2 f;
    asm("mov.b64 {%0, %1}, %2;" : "=f"(f.x), "=f"(f.y) : "l"(v));
    return f;
}

// ---------------- CSR build -------------------------------------------------
// hist also zeroes g_pool / g_cnt (consumed at end of previous call).
// g_deg is zero at module load and re-zeroed by scan_kernel every call,
// so every call sees identical state: deterministic.
__global__ void __launch_bounds__(256) hist_kernel(const int* __restrict__ ei) {
    int i = blockIdx.x * 256 + threadIdx.x;
    if (i < cG * cH) g_pool[i] = 0.f;
    if (i < cG) g_cnt[i] = 0;
    if (i < cE) atomicAdd(&g_deg[ei[cE + i]], 1);
}

__global__ void __launch_bounds__(1024) scan_kernel() {
    const int TP = (cN + 1023) / 1024;  // 98
    int t = threadIdx.x;
    int s0 = t * TP, s1 = min(s0 + TP, cN);
    int ls = 0;
    for (int i = s0; i < s1; i++) ls += g_deg[i];
    __shared__ int ps[1024];
    ps[t] = ls;
    __syncthreads();
    for (int off = 1; off < 1024; off <<= 1) {
        int v = (t >= off) ? ps[t - off] : 0;
        __syncthreads();
        ps[t] += v;
        __syncthreads();
    }
    int run = ps[t] - ls;
    for (int i = s0; i < s1; i++) {
        int d = g_deg[i];
        g_deg[i] = 0;          // restore for next call's hist
        g_rowptr[i] = run;
        g_woff[i]   = run;
        run += d;
    }
    if (t == 0) g_rowptr[cN] = cE;
}

// scatter + permute edge_attr into CSR (dst-sorted) order, fused
__global__ void __launch_bounds__(256) scatter_kernel(
    const int* __restrict__ ei, const float* __restrict__ ea)
{
    int e = blockIdx.x * 256 + threadIdx.x;
    if (e >= cE) return;
    int s = ei[e], d = ei[cE + e];
    int pos = atomicAdd(&g_woff[d], 1);
    g_src[pos] = s;
    const float4* sp = (const float4*)(ea + (size_t)e * cDE);
    float4 a = sp[0], b = sp[1], c = sp[2], dd = sp[3];
    float4* dp = (float4*)(g_ea_perm + (size_t)pos * cDE);
    dp[0] = a; dp[1] = b; dp[2] = c; dp[3] = dd;
}

// ---------------- edge message + gather aggregate (two-phase) --------------
// Per chunk of 128 edges:
//   phase 1: warps split edges evenly (16 each); lanes = channels; compute
//            m = relu(x[src] + ea @ ew^T + eb) with NO accumulator chain;
//            store messages to smem.
//   phase 2: warp per node sums its CSR segment from smem.
template <int C>
__global__ void __launch_bounds__(256) gather_kernel(
    const float* __restrict__ xin, int use_internal,
    const float* __restrict__ ew, const float* __restrict__ eb)
{
    constexpr int CPT   = C / 32;   // 1 (layer0) or 2
    constexpr int KP    = cDE / 2;  // 8 k-pairs
    constexpr int CHUNK = 128;

    __shared__ __align__(16) float ea_s[CHUNK * cDE];
    __shared__ __align__(16) float msg_s[CHUNK * C];
    __shared__ int src_s[CHUNK];

    const float* x = use_internal ? g_x : xin;
    int t = threadIdx.x;

    if (blockIdx.x == 0 && t < cH) { g_sum[t] = 0.f; g_sumsq[t] = 0.f; }

    int lane = t & 31;
    int w = t >> 5;
    int c0 = lane * CPT;

    ull wreg[CPT][KP];
    float ebr[CPT];
    #pragma unroll
    for (int c = 0; c < CPT; c++) {
        #pragma unroll
        for (int j = 0; j < KP; j++)
            wreg[c][j] = *(const ull*)&ew[(c0 + c) * cDE + 2 * j];
        ebr[c] = eb[c0 + c];
    }

    int n0 = blockIdx.x * 8;
    int node = n0 + w;
    int es_blk = g_rowptr[n0], ee_blk = g_rowptr[n0 + 8];
    int es = g_rowptr[node], ee = g_rowptr[node + 1];

    float acc[CPT];
    #pragma unroll
    for (int c = 0; c < CPT; c++) acc[c] = 0.f;

    for (int base = es_blk; base < ee_blk; base += CHUNK) {
        int cnt = min(CHUNK, ee_blk - base);
        __syncthreads();   // msg_s / ea_s safe to overwrite
        for (int i = t; i < cnt * (cDE / 4); i += 256)
            ((float4*)ea_s)[i] = ((const float4*)g_ea_perm)[(size_t)base * 4 + i];
        for (int i = t; i < cnt; i += 256) src_s[i] = g_src[base + i];
        __syncthreads();

        // ---- phase 1: balanced edge-parallel message compute ----
        int p0 = w * 16, p1 = min(p0 + 16, cnt);
        int e = p0;
        for (; e + 4 <= p1; e += 4) {
            int ss[4];
            #pragma unroll
            for (int r = 0; r < 4; r++) ss[r] = src_s[e + r];
            float xa[4], xb[4];
            if (CPT == 2) {
                #pragma unroll
                for (int r = 0; r < 4; r++) {
                    float2 xx = *(const float2*)(x + (size_t)ss[r] * C + c0);
                    xa[r] = xx.x; xb[r] = xx.y;
                }
            } else {
                #pragma unroll
                for (int r = 0; r < 4; r++) xa[r] = x[(size_t)ss[r] * C + c0];
            }
            #pragma unroll
            for (int r = 0; r < 4; r++) {
                const ull* eap = (const ull*)&ea_s[(e + r) * cDE];
                if (CPT == 2) {
                    ull d0 = pack2(ebr[0], 0.f), d1 = pack2(ebr[1], 0.f);
                    #pragma unroll
                    for (int j = 0; j < KP; j++) {
                        ull ev = eap[j];
                        d0 = ffma2(wreg[0][j], ev, d0);
                        d1 = ffma2(wreg[1][j], ev, d1);
                    }
                    float2 pa = unpack2(d0), pb = unpack2(d1);
                    float2 m;
                    m.x = fmaxf(xa[r] + pa.x + pa.y, 0.f);
                    m.y = fmaxf(xb[r] + pb.x + pb.y, 0.f);
                    *(float2*)&msg_s[(e + r) * C + c0] = m;
                } else {
                    ull d0 = pack2(ebr[0], 0.f);
                    #pragma unroll
                    for (int j = 0; j < KP; j++) d0 = ffma2(wreg[0][j], eap[j], d0);
                    float2 pa = unpack2(d0);
                    msg_s[(e + r) * C + c0] = fmaxf(xa[r] + pa.x + pa.y, 0.f);
                }
            }
        }
        for (; e < p1; e++) {
            int s = src_s[e];
            const ull* eap = (const ull*)&ea_s[e * cDE];
            #pragma unroll
            for (int c = 0; c < CPT; c++) {
                ull d2 = pack2(ebr[c], 0.f);
                #pragma unroll
                for (int j = 0; j < KP; j++) d2 = ffma2(wreg[c][j], eap[j], d2);
                float2 p = unpack2(d2);
                float xv = x[(size_t)s * C + c0 + c];
                msg_s[e * C + c0 + c] = fmaxf(xv + p.x + p.y, 0.f);
            }
        }
        __syncthreads();

        // ---- phase 2: per-node reduction from smem ----
        int e0 = max(es, base), e1 = min(ee, base + cnt);
        if (CPT == 2) {
            #pragma unroll 4
            for (int e2 = e0; e2 < e1; e2++) {
                float2 m = *(const float2*)&msg_s[(e2 - base) * C + c0];
                acc[0] += m.x; acc[1] += m.y;
            }
        } else {
            #pragma unroll 4
            for (int e2 = e0; e2 < e1; e2++)
                acc[0] += msg_s[(e2 - base) * C + c0];
        }
    }

    if (CPT == 2) {
        float2 xx = *(const float2*)(x + (size_t)node * C + c0);
        *(float2*)(g_u + (size_t)node * C + c0) =
            make_float2(xx.x + acc[0], xx.y + acc[1]);
    } else {
        g_u[(size_t)node * C + c0] = x[(size_t)node * C + c0] + acc[0];
    }
}

// ---------------- node update: h2 = relu(relu(u W1^T + b1) W2^T + b2) ------
template <int CIN>
__global__ void __launch_bounds__(256, 2) node_kernel(
    const float* __restrict__ w1, const float* __restrict__ b1,
    const float* __restrict__ w2, const float* __restrict__ b2)
{
    constexpr int KP1 = CIN / 2;   // 16 or 32
    constexpr int US  = KP1 + 1;
    constexpr int KP2 = cH / 2;    // 32
    constexpr int HS  = KP2 + 1;   // 33
    constexpr int WS  = KP2 + 1;

    extern __shared__ __align__(16) ull dyn[];
    ull* us2 = dyn;                    // [128 * US]
    ull* ws2 = us2 + 128 * US;         // [64 * WS]
    ull* hs2 = ws2 + 64 * WS;          // [128 * HS]
    float* hsf = (float*)hs2;

    int t = threadIdx.x;
    int lane = t & 31;
    int w = t >> 5;
    int n0 = blockIdx.x * 128;

    for (int i = t; i < 128 * KP1; i += 256) {
        int n = i / KP1, j = i % KP1;
        us2[n * US + j] = (n0 + n < cN)
            ? *(const ull*)&g_u[(size_t)(n0 + n) * CIN + 2 * j] : 0ull;
    }
    for (int i = t; i < cH * KP1; i += 256) {
        int r = i / KP1, j = i % KP1;
        ws2[r * WS + j] = ((const ull*)w1)[i];
    }
    __syncthreads();

    // ---- GEMM 1 ----
    ull acc2[4][8];
    #pragma unroll
    for (int j = 0; j < 8; j++) {
        ull b = pack2(b1[w * 8 + j], 0.f);
        #pragma unroll
        for (int i = 0; i < 4; i++) acc2[i][j] = b;
    }
    for (int kp = 0; kp < KP1; kp++) {
        ull wt[8], uv[4];
        #pragma unroll
        for (int j = 0; j < 8; j++) wt[j] = ws2[(w * 8 + j) * WS + kp];
        #pragma unroll
        for (int i = 0; i < 4; i++) uv[i] = us2[(lane + 32 * i) * US + kp];
        #pragma unroll
        for (int i = 0; i < 4; i++)
            #pragma unroll
            for (int j = 0; j < 8; j++)
                acc2[i][j] = ffma2(wt[j], uv[i], acc2[i][j]);
    }
    #pragma unroll
    for (int i = 0; i < 4; i++) {
        int n = lane + 32 * i;
        #pragma unroll
        for (int j = 0; j < 8; j += 2) {
            float2 pa = unpack2(acc2[i][j]);
            float2 pb = unpack2(acc2[i][j + 1]);
            ull pk = pack2(fmaxf(pa.x + pa.y, 0.f), fmaxf(pb.x + pb.y, 0.f));
            *(ull*)&hsf[n * (2 * HS) + w * 8 + j] = pk;
        }
    }
    __syncthreads();

    for (int i = t; i < cH * KP2; i += 256) {
        int r = i / KP2, j = i % KP2;
        ws2[r * WS + j] = ((const ull*)w2)[i];
    }
    __syncthreads();

    // ---- GEMM 2 ----
    #pragma unroll
    for (int j = 0; j < 8; j++) {
        ull b = pack2(b2[w * 8 + j], 0.f);
        #pragma unroll
        for (int i = 0; i < 4; i++) acc2[i][j] = b;
    }
    for (int kp = 0; kp < KP2; kp++) {
        ull wt[8], uv[4];
        #pragma unroll
        for (int j = 0; j < 8; j++) wt[j] = ws2[(w * 8 + j) * WS + kp];
        #pragma unroll
        for (int i = 0; i < 4; i++) uv[i] = hs2[(lane + 32 * i) * HS + kp];
        #pragma unroll
        for (int i = 0; i < 4; i++)
            #pragma unroll
            for (int j = 0; j < 8; j++)
                acc2[i][j] = ffma2(wt[j], uv[i], acc2[i][j]);
    }

    float v[4][8];
    float s[8], q[8];
    #pragma unroll
    for (int j = 0; j < 8; j++) { s[j] = 0.f; q[j] = 0.f; }
    #pragma unroll
    for (int i = 0; i < 4; i++) {
        bool valid = (n0 + lane + 32 * i) < cN;
        #pragma unroll
        for (int j = 0; j < 8; j++) {
            float2 p = unpack2(acc2[i][j]);
            float vv = valid ? fmaxf(p.x + p.y, 0.f) : 0.f;
            v[i][j] = vv;
            s[j] += vv; q[j] += vv * vv;
        }
    }
    #pragma unroll
    for (int j = 0; j < 8; j++) {
        #pragma unroll
        for (int off = 16; off > 0; off >>= 1) {
            s[j] += __shfl_xor_sync(0xffffffffu, s[j], off);
            q[j] += __shfl_xor_sync(0xffffffffu, q[j], off);
        }
    }
    if (lane == 0) {
        #pragma unroll
        for (int j = 0; j < 8; j++) {
            atomicAdd(&g_sum[w * 8 + j], s[j]);
            atomicAdd(&g_sumsq[w * 8 + j], q[j]);
        }
    }

    __syncthreads();
    #pragma unroll
    for (int i = 0; i < 4; i++) {
        int n = lane + 32 * i;
        #pragma unroll
        for (int j = 0; j < 8; j += 2) {
            ull pk = pack2(v[i][j], v[i][j + 1]);
            *(ull*)&hsf[n * (2 * HS) + w * 8 + j] = pk;
        }
    }
    __syncthreads();
    for (int i = t; i < 128 * cH / 2; i += 256) {
        int n = i / KP2, j = i % KP2;
        if (n0 + n < cN)
            *(ull*)&g_h[(size_t)(n0 + n) * cH + 2 * j] = *(ull*)&hsf[n * (2 * HS) + 2 * j];
    }
}

// ---------------- BN normalize (+ relu), optionally fused graph pooling ----
__global__ void __launch_bounds__(256) norm_kernel(
    const float* __restrict__ gamma, const float* __restrict__ beta,
    const int* __restrict__ batch, int last)
{
    int idx = blockIdx.x * 256 + threadIdx.x;
    if (idx >= cN * 16) return;
    int node = idx >> 4;
    int c0 = (idx & 15) * 4;
    float4 h = ((const float4*)g_h)[idx];
    float v[4] = {h.x, h.y, h.z, h.w};
    #pragma unroll
    for (int j = 0; j < 4; j++) {
        int c = c0 + j;
        float mu  = g_sum[c]   * (1.f / cN);
        float var = g_sumsq[c] * (1.f / cN) - mu * mu;
        float sc  = rsqrtf(var + 1e-5f) * gamma[c];
        v[j] = fmaxf((v[j] - mu) * sc + beta[c], 0.f);
    }
    ((float4*)g_x)[idx] = make_float4(v[0], v[1], v[2], v[3]);
    if (last) {
        int b = batch[node];
        red_add_v4(&g_pool[b * cH + c0], v[0], v[1], v[2], v[3]);
        if (c0 == 0) atomicAdd(&g_cnt[b], 1);
    }
}

// ---------------- pooled mean + MLP head -----------------------------------
__global__ void __launch_bounds__(128) head_kernel(
    const float* __restrict__ hw1, const float* __restrict__ hb1,
    const float* __restrict__ hw2, const float* __restrict__ hb2,
    float* __restrict__ out)
{
    __shared__ float p[cH], z[cMH];
    int g = blockIdx.x, t = threadIdx.x;
    if (t < cH) p[t] = g_pool[g * cH + t] / fmaxf((float)g_cnt[g], 1.f);
    __syncthreads();
    float acc = hb1[t];
    for (int c = 0; c < cH; c++) acc += p[c] * hw1[t * cH + c];
    z[t] = fmaxf(acc, 0.f);
    __syncthreads();
    if (t < cOUT) {
        float a = hb2[t];
        for (int m = 0; m < cMH; m++) a += z[m] * hw2[t * cMH + m];
        out[g * cOUT + t] = a;
    }
}

// ---------------- launch ----------------------------------------------------
extern "C" void kernel_launch(void* const* d_in, const int* in_sizes, int n_in,
                              void* d_out, int out_size)
{
    const float* x    = (const float*)d_in[0];
    const int*   ei   = (const int*)  d_in[1];
    const float* ea   = (const float*)d_in[2];
    const int*   batch= (const int*)  d_in[3];
    const float* l0ew = (const float*)d_in[4];
    const float* l0eb = (const float*)d_in[5];
    const float* l0w1 = (const float*)d_in[6];
    const float* l0b1 = (const float*)d_in[7];
    const float* l0w2 = (const float*)d_in[8];
    const float* l0b2 = (const float*)d_in[9];
    const float* ewA  = (const float*)d_in[10];  // [3, H, DE]
    const float* ebA  = (const float*)d_in[11];  // [3, H]
    const float* w1A  = (const float*)d_in[12];  // [3, H, H]
    const float* b1A  = (const float*)d_in[13];
    const float* w2A  = (const float*)d_in[14];
    const float* b2A  = (const float*)d_in[15];
    const float* bng  = (const float*)d_in[16];  // [4, H]
    const float* bnb  = (const float*)d_in[17];
    const float* hw1  = (const float*)d_in[18];
    const float* hb1  = (const float*)d_in[19];
    const float* hw2  = (const float*)d_in[20];
    const float* hb2  = (const float*)d_in[21];
    float* out = (float*)d_out;

    const int EB = (cE + 255) / 256;       // 6250
    const int GB = cN / 8;                 // 12500
    const int NB = (cN + 127) / 128;       // 782
    const int MB = cN * 16 / 256;          // 6250

    const int SM32 = (128 * (cDIN / 2 + 1) + cH * 33 + 128 * 33) * 8;
    const int SM64 = (128 * (cH   / 2 + 1) + cH * 33 + 128 * 33) * 8;
    cudaFuncSetAttribute(node_kernel<cDIN>,
                         cudaFuncAttributeMaxDynamicSharedMemorySize, SM32);
    cudaFuncSetAttribute(node_kernel<cH>,
                         cudaFuncAttributeMaxDynamicSharedMemorySize, SM64);

    // CSR build (by dst) + edge_attr permutation
    hist_kernel<<<EB, 256>>>(ei);
    scan_kernel<<<1, 1024>>>();
    scatter_kernel<<<EB, 256>>>(ei, ea);

    // layer 0 (CIN = 32) — gather is the 4th launch (ncu capture target)
    gather_kernel<cDIN><<<GB, 256>>>(x, 0, l0ew, l0eb);
    node_kernel<cDIN><<<NB, 256, SM32>>>(l0w1, l0b1, l0w2, l0b2);
    norm_kernel<<<MB, 256>>>(bng, bnb, batch, 0);

    // layers 1..3 (CIN = 64)
    for (int i = 0; i < 3; i++) {
        int last = (i == 2) ? 1 : 0;
        gather_kernel<cH><<<GB, 256>>>(nullptr, 1,
                                       ewA + (size_t)i * cH * cDE, ebA + (size_t)i * cH);
        node_kernel<cH><<<NB, 256, SM64>>>(w1A + (size_t)i * cH * cH, b1A + (size_t)i * cH,
                                           w2A + (size_t)i * cH * cH, b2A + (size_t)i * cH);
        norm_kernel<<<MB, 256>>>(bng + (size_t)(i + 1) * cH,
                                 bnb + (size_t)(i + 1) * cH, batch, last);
    }

    head_kernel<<<cG, 128>>>(hw1, hb1, hw2, hb2, out);
}

// round 9
// speedup vs baseline: 2.0210x; 2.0210x over previous
#include <cuda_runtime.h>

#define DEV_INLINE __device__ __forceinline__

constexpr int cN   = 100000;   // nodes
constexpr int cE   = 1600000;  // edges
constexpr int cDIN = 32;       // node in channels
constexpr int cDE  = 16;       // edge feature dim
constexpr int cH   = 64;       // hidden
constexpr int cMH  = 128;      // mlp hidden
constexpr int cOUT = 10;       // out channels
constexpr int cG   = 128;      // graphs
constexpr int EPW  = 32;       // edges per warp (segmented gather)

typedef unsigned long long ull;

// ---------------- scratch (device globals; no allocation allowed) ----------
__device__ __align__(16) float g_u[cN * cH];       // x + agg (node MLP input)
__device__ __align__(16) float g_h[cN * cH];       // node MLP output (pre-BN)
__device__ __align__(16) float g_x[cN * cH];       // post-BN activations
__device__ __align__(16) float g_ea_perm[(size_t)cE * cDE];  // ea in CSR order
__device__ __align__(16) int   g_src[cE];          // src in CSR order
__device__ __align__(16) int   g_dst[cE];          // dst in CSR order (sorted)
__device__ __align__(16) int   g_deg[cN];          // zeroed by scan (self-restoring)
__device__ __align__(16) int   g_woff[cN];
__device__ __align__(16) int   g_rowptr[cN + 1];
__device__ __align__(16) float g_sum[cH];
__device__ __align__(16) float g_sumsq[cH];
__device__ __align__(16) float g_pool[cG * cH];
__device__ __align__(16) int   g_cnt[cG];

DEV_INLINE void red_add_v4(float* p, float a, float b, float c, float d) {
    asm volatile("red.global.add.v4.f32 [%0], {%1,%2,%3,%4};"
                 :: "l"(p), "f"(a), "f"(b), "f"(c), "f"(d) : "memory");
}
DEV_INLINE void red_add_v2(float* p, float a, float b) {
    asm volatile("red.global.add.v2.f32 [%0], {%1,%2};"
                 :: "l"(p), "f"(a), "f"(b) : "memory");
}
DEV_INLINE void red_add_1(float* p, float a) {
    asm volatile("red.global.add.f32 [%0], %1;" :: "l"(p), "f"(a) : "memory");
}
DEV_INLINE ull ffma2(ull a, ull b, ull c) {
    ull d;
    asm("fma.rn.f32x2 %0, %1, %2, %3;" : "=l"(d) : "l"(a), "l"(b), "l"(c));
    return d;
}
DEV_INLINE ull pack2(float lo, float hi) {
    ull v;
    asm("mov.b64 %0, {%1, %2};" : "=l"(v) : "f"(lo), "f"(hi));
    return v;
}
DEV_INLINE float2 unpack2(ull v) {
    float2 f;
    asm("mov.b64 {%0, %1}, %2;" : "=f"(f.x), "=f"(f.y) : "l"(v));
    return f;
}

// ---------------- CSR build -------------------------------------------------
// hist also zeroes g_pool / g_cnt (consumed at end of previous call).
// g_deg is zero at load and re-zeroed by scan_kernel each call: deterministic.
__global__ void __launch_bounds__(256) hist_kernel(const int* __restrict__ ei) {
    int i = blockIdx.x * 256 + threadIdx.x;
    if (i < cG * cH) g_pool[i] = 0.f;
    if (i < cG) g_cnt[i] = 0;
    if (i < cE) atomicAdd(&g_deg[ei[cE + i]], 1);
}

__global__ void __launch_bounds__(1024) scan_kernel() {
    const int TP = (cN + 1023) / 1024;  // 98
    int t = threadIdx.x;
    int s0 = t * TP, s1 = min(s0 + TP, cN);
    int ls = 0;
    for (int i = s0; i < s1; i++) ls += g_deg[i];
    __shared__ int ps[1024];
    ps[t] = ls;
    __syncthreads();
    for (int off = 1; off < 1024; off <<= 1) {
        int v = (t >= off) ? ps[t - off] : 0;
        __syncthreads();
        ps[t] += v;
        __syncthreads();
    }
    int run = ps[t] - ls;
    for (int i = s0; i < s1; i++) {
        int d = g_deg[i];
        g_deg[i] = 0;          // restore for next call's hist
        g_rowptr[i] = run;
        g_woff[i]   = run;
        run += d;
    }
    if (t == 0) g_rowptr[cN] = cE;
}

// scatter + permute edge_attr into CSR (dst-sorted) order, fused
__global__ void __launch_bounds__(256) scatter_kernel(
    const int* __restrict__ ei, const float* __restrict__ ea)
{
    int e = blockIdx.x * 256 + threadIdx.x;
    if (e >= cE) return;
    int s = ei[e], d = ei[cE + e];
    int pos = atomicAdd(&g_woff[d], 1);
    g_src[pos] = s;
    g_dst[pos] = d;
    const float4* sp = (const float4*)(ea + (size_t)e * cDE);
    float4 a = sp[0], b = sp[1], c = sp[2], dd = sp[3];
    float4* dp = (float4*)(g_ea_perm + (size_t)pos * cDE);
    dp[0] = a; dp[1] = b; dp[2] = c; dp[3] = dd;
}

// ---------------- g_u init for layer 0: g_u = x -----------------------------
__global__ void __launch_bounds__(256) copyu_kernel(const float* __restrict__ x) {
    int i = blockIdx.x * 256 + threadIdx.x;
    if (i < cN * cDIN / 4) ((float4*)g_u)[i] = ((const float4*)x)[i];
}

// ---------------- segmented gather: g_u[d] += relu(x[src]+ea@W^T+b) --------
// Each warp owns 32 consecutive CSR edges (dst-sorted). Lanes = channels
// (CPT per lane). Accumulate while dst unchanged; flush via red.add at
// segment boundaries. No block syncs, perfect edge balance.
template <int C>
__global__ void __launch_bounds__(256) gather_kernel(
    const float* __restrict__ xin, int use_internal,
    const float* __restrict__ ew, const float* __restrict__ eb)
{
    constexpr int CPT = C / 32;   // 1 (layer0) or 2
    constexpr int KP  = cDE / 2;  // 8 k-pairs

    __shared__ __align__(16) float ea_s[8][EPW * cDE];
    __shared__ int src_s[8][EPW];
    __shared__ int dst_s[8][EPW];

    const float* x = use_internal ? g_x : xin;
    int t = threadIdx.x;
    int lane = t & 31;
    int w = t >> 5;

    if (blockIdx.x == 0 && t < cH) { g_sum[t] = 0.f; g_sumsq[t] = 0.f; }

    int c0 = lane * CPT;
    ull wreg[CPT][KP];
    float ebr[CPT];
    #pragma unroll
    for (int c = 0; c < CPT; c++) {
        #pragma unroll
        for (int j = 0; j < KP; j++)
            wreg[c][j] = *(const ull*)&ew[(c0 + c) * cDE + 2 * j];
        ebr[c] = eb[c0 + c];
    }

    int e0 = (blockIdx.x * 8 + w) * EPW;   // grid sized so e0+EPW <= cE exactly

    // warp-local staging (coalesced)
    src_s[w][lane] = g_src[e0 + lane];
    dst_s[w][lane] = g_dst[e0 + lane];
    {
        const float4* gp = (const float4*)(g_ea_perm + (size_t)e0 * cDE);
        float4* sp = (float4*)ea_s[w];
        #pragma unroll
        for (int i = 0; i < EPW * cDE / 4 / 32; i++)   // 4 iters
            sp[lane + 32 * i] = gp[lane + 32 * i];
    }
    __syncwarp();

    float acc0 = 0.f, acc1 = 0.f;
    int cur = dst_s[w][0];

    for (int g = 0; g < EPW; g += 4) {
        int ss[4];
        #pragma unroll
        for (int r = 0; r < 4; r++) ss[r] = src_s[w][g + r];
        float xa[4], xb[4];
        if (CPT == 2) {
            #pragma unroll
            for (int r = 0; r < 4; r++) {
                float2 xx = *(const float2*)(x + (size_t)ss[r] * C + c0);
                xa[r] = xx.x; xb[r] = xx.y;
            }
        } else {
            #pragma unroll
            for (int r = 0; r < 4; r++) xa[r] = x[(size_t)ss[r] * C + c0];
        }
        #pragma unroll
        for (int r = 0; r < 4; r++) {
            const ull* eap = (const ull*)&ea_s[w][(g + r) * cDE];
            int d = dst_s[w][g + r];
            if (d != cur) {   // warp-uniform branch
                if (CPT == 2) red_add_v2(&g_u[(size_t)cur * C + c0], acc0, acc1);
                else          red_add_1(&g_u[(size_t)cur * C + c0], acc0);
                acc0 = 0.f; acc1 = 0.f;
                cur = d;
            }
            if (CPT == 2) {
                ull d0 = pack2(ebr[0], 0.f), d1 = pack2(ebr[1], 0.f);
                #pragma unroll
                for (int j = 0; j < KP; j++) {
                    ull ev = eap[j];
                    d0 = ffma2(wreg[0][j], ev, d0);
                    d1 = ffma2(wreg[1][j], ev, d1);
                }
                float2 pa = unpack2(d0), pb = unpack2(d1);
                acc0 += fmaxf(xa[r] + pa.x + pa.y, 0.f);
                acc1 += fmaxf(xb[r] + pb.x + pb.y, 0.f);
            } else {
                ull d0 = pack2(ebr[0], 0.f);
                #pragma unroll
                for (int j = 0; j < KP; j++) d0 = ffma2(wreg[0][j], eap[j], d0);
                float2 pa = unpack2(d0);
                acc0 += fmaxf(xa[r] + pa.x + pa.y, 0.f);
            }
        }
    }
    if (CPT == 2) red_add_v2(&g_u[(size_t)cur * C + c0], acc0, acc1);
    else          red_add_1(&g_u[(size_t)cur * C + c0], acc0);
}

// ---------------- node update: h2 = relu(relu(u W1^T + b1) W2^T + b2) ------
template <int CIN>
__global__ void __launch_bounds__(256, 2) node_kernel(
    const float* __restrict__ w1, const float* __restrict__ b1,
    const float* __restrict__ w2, const float* __restrict__ b2)
{
    constexpr int KP1 = CIN / 2;   // 16 or 32
    constexpr int US  = KP1 + 1;
    constexpr int KP2 = cH / 2;    // 32
    constexpr int HS  = KP2 + 1;   // 33
    constexpr int WS  = KP2 + 1;

    extern __shared__ __align__(16) ull dyn[];
    ull* us2 = dyn;                    // [128 * US]
    ull* ws2 = us2 + 128 * US;         // [64 * WS]
    ull* hs2 = ws2 + 64 * WS;          // [128 * HS]
    float* hsf = (float*)hs2;

    int t = threadIdx.x;
    int lane = t & 31;
    int w = t >> 5;
    int n0 = blockIdx.x * 128;

    for (int i = t; i < 128 * KP1; i += 256) {
        int n = i / KP1, j = i % KP1;
        us2[n * US + j] = (n0 + n < cN)
            ? *(const ull*)&g_u[(size_t)(n0 + n) * CIN + 2 * j] : 0ull;
    }
    for (int i = t; i < cH * KP1; i += 256) {
        int r = i / KP1, j = i % KP1;
        ws2[r * WS + j] = ((const ull*)w1)[i];
    }
    __syncthreads();

    // ---- GEMM 1 ----
    ull acc2[4][8];
    #pragma unroll
    for (int j = 0; j < 8; j++) {
        ull b = pack2(b1[w * 8 + j], 0.f);
        #pragma unroll
        for (int i = 0; i < 4; i++) acc2[i][j] = b;
    }
    for (int kp = 0; kp < KP1; kp++) {
        ull wt[8], uv[4];
        #pragma unroll
        for (int j = 0; j < 8; j++) wt[j] = ws2[(w * 8 + j) * WS + kp];
        #pragma unroll
        for (int i = 0; i < 4; i++) uv[i] = us2[(lane + 32 * i) * US + kp];
        #pragma unroll
        for (int i = 0; i < 4; i++)
            #pragma unroll
            for (int j = 0; j < 8; j++)
                acc2[i][j] = ffma2(wt[j], uv[i], acc2[i][j]);
    }
    #pragma unroll
    for (int i = 0; i < 4; i++) {
        int n = lane + 32 * i;
        #pragma unroll
        for (int j = 0; j < 8; j += 2) {
            float2 pa = unpack2(acc2[i][j]);
            float2 pb = unpack2(acc2[i][j + 1]);
            ull pk = pack2(fmaxf(pa.x + pa.y, 0.f), fmaxf(pb.x + pb.y, 0.f));
            *(ull*)&hsf[n * (2 * HS) + w * 8 + j] = pk;
        }
    }
    __syncthreads();

    for (int i = t; i < cH * KP2; i += 256) {
        int r = i / KP2, j = i % KP2;
        ws2[r * WS + j] = ((const ull*)w2)[i];
    }
    __syncthreads();

    // ---- GEMM 2 ----
    #pragma unroll
    for (int j = 0; j < 8; j++) {
        ull b = pack2(b2[w * 8 + j], 0.f);
        #pragma unroll
        for (int i = 0; i < 4; i++) acc2[i][j] = b;
    }
    for (int kp = 0; kp < KP2; kp++) {
        ull wt[8], uv[4];
        #pragma unroll
        for (int j = 0; j < 8; j++) wt[j] = ws2[(w * 8 + j) * WS + kp];
        #pragma unroll
        for (int i = 0; i < 4; i++) uv[i] = hs2[(lane + 32 * i) * HS + kp];
        #pragma unroll
        for (int i = 0; i < 4; i++)
            #pragma unroll
            for (int j = 0; j < 8; j++)
                acc2[i][j] = ffma2(wt[j], uv[i], acc2[i][j]);
    }

    float v[4][8];
    float s[8], q[8];
    #pragma unroll
    for (int j = 0; j < 8; j++) { s[j] = 0.f; q[j] = 0.f; }
    #pragma unroll
    for (int i = 0; i < 4; i++) {
        bool valid = (n0 + lane + 32 * i) < cN;
        #pragma unroll
        for (int j = 0; j < 8; j++) {
            float2 p = unpack2(acc2[i][j]);
            float vv = valid ? fmaxf(p.x + p.y, 0.f) : 0.f;
            v[i][j] = vv;
            s[j] += vv; q[j] += vv * vv;
        }
    }
    #pragma unroll
    for (int j = 0; j < 8; j++) {
        #pragma unroll
        for (int off = 16; off > 0; off >>= 1) {
            s[j] += __shfl_xor_sync(0xffffffffu, s[j], off);
            q[j] += __shfl_xor_sync(0xffffffffu, q[j], off);
        }
    }
    if (lane == 0) {
        #pragma unroll
        for (int j = 0; j < 8; j++) {
            atomicAdd(&g_sum[w * 8 + j], s[j]);
            atomicAdd(&g_sumsq[w * 8 + j], q[j]);
        }
    }

    __syncthreads();
    #pragma unroll
    for (int i = 0; i < 4; i++) {
        int n = lane + 32 * i;
        #pragma unroll
        for (int j = 0; j < 8; j += 2) {
            ull pk = pack2(v[i][j], v[i][j + 1]);
            *(ull*)&hsf[n * (2 * HS) + w * 8 + j] = pk;
        }
    }
    __syncthreads();
    for (int i = t; i < 128 * cH / 2; i += 256) {
        int n = i / KP2, j = i % KP2;
        if (n0 + n < cN)
            *(ull*)&g_h[(size_t)(n0 + n) * cH + 2 * j] = *(ull*)&hsf[n * (2 * HS) + 2 * j];
    }
}

// ---------------- BN normalize (+relu); writes g_x and (if !last) g_u ------
__global__ void __launch_bounds__(256) norm_kernel(
    const float* __restrict__ gamma, const float* __restrict__ beta,
    const int* __restrict__ batch, int last)
{
    int idx = blockIdx.x * 256 + threadIdx.x;
    if (idx >= cN * 16) return;
    int node = idx >> 4;
    int c0 = (idx & 15) * 4;
    float4 h = ((const float4*)g_h)[idx];
    float v[4] = {h.x, h.y, h.z, h.w};
    #pragma unroll
    for (int j = 0; j < 4; j++) {
        int c = c0 + j;
        float mu  = g_sum[c]   * (1.f / cN);
        float var = g_sumsq[c] * (1.f / cN) - mu * mu;
        float sc  = rsqrtf(var + 1e-5f) * gamma[c];
        v[j] = fmaxf((v[j] - mu) * sc + beta[c], 0.f);
    }
    float4 vv = make_float4(v[0], v[1], v[2], v[3]);
    ((float4*)g_x)[idx] = vv;
    if (!last) {
        ((float4*)g_u)[idx] = vv;     // seed u = x for next layer's gather
    } else {
        int b = batch[node];
        red_add_v4(&g_pool[b * cH + c0], v[0], v[1], v[2], v[3]);
        if (c0 == 0) atomicAdd(&g_cnt[b], 1);
    }
}

// ---------------- pooled mean + MLP head -----------------------------------
__global__ void __launch_bounds__(128) head_kernel(
    const float* __restrict__ hw1, const float* __restrict__ hb1,
    const float* __restrict__ hw2, const float* __restrict__ hb2,
    float* __restrict__ out)
{
    __shared__ float p[cH], z[cMH];
    int g = blockIdx.x, t = threadIdx.x;
    if (t < cH) p[t] = g_pool[g * cH + t] / fmaxf((float)g_cnt[g], 1.f);
    __syncthreads();
    float acc = hb1[t];
    for (int c = 0; c < cH; c++) acc += p[c] * hw1[t * cH + c];
    z[t] = fmaxf(acc, 0.f);
    __syncthreads();
    if (t < cOUT) {
        float a = hb2[t];
        for (int m = 0; m < cMH; m++) a += z[m] * hw2[t * cMH + m];
        out[g * cOUT + t] = a;
    }
}

// ---------------- launch ----------------------------------------------------
extern "C" void kernel_launch(void* const* d_in, const int* in_sizes, int n_in,
                              void* d_out, int out_size)
{
    const float* x    = (const float*)d_in[0];
    const int*   ei   = (const int*)  d_in[1];
    const float* ea   = (const float*)d_in[2];
    const int*   batch= (const int*)  d_in[3];
    const float* l0ew = (const float*)d_in[4];
    const float* l0eb = (const float*)d_in[5];
    const float* l0w1 = (const float*)d_in[6];
    const float* l0b1 = (const float*)d_in[7];
    const float* l0w2 = (const float*)d_in[8];
    const float* l0b2 = (const float*)d_in[9];
    const float* ewA  = (const float*)d_in[10];  // [3, H, DE]
    const float* ebA  = (const float*)d_in[11];  // [3, H]
    const float* w1A  = (const float*)d_in[12];  // [3, H, H]
    const float* b1A  = (const float*)d_in[13];
    const float* w2A  = (const float*)d_in[14];
    const float* b2A  = (const float*)d_in[15];
    const float* bng  = (const float*)d_in[16];  // [4, H]
    const float* bnb  = (const float*)d_in[17];
    const float* hw1  = (const float*)d_in[18];
    const float* hb1  = (const float*)d_in[19];
    const float* hw2  = (const float*)d_in[20];
    const float* hb2  = (const float*)d_in[21];
    float* out = (float*)d_out;

    const int EB = (cE + 255) / 256;       // 6250
    const int GB = cE / (8 * EPW);         // 6250 (exact: 1.6M / 256)
    const int NB = (cN + 127) / 128;       // 782
    const int MB = cN * 16 / 256;          // 6250
    const int CB = cN * cDIN / 4 / 256;    // 3125

    const int SM32 = (128 * (cDIN / 2 + 1) + cH * 33 + 128 * 33) * 8;
    const int SM64 = (128 * (cH   / 2 + 1) + cH * 33 + 128 * 33) * 8;
    cudaFuncSetAttribute(node_kernel<cDIN>,
                         cudaFuncAttributeMaxDynamicSharedMemorySize, SM32);
    cudaFuncSetAttribute(node_kernel<cH>,
                         cudaFuncAttributeMaxDynamicSharedMemorySize, SM64);

    // CSR build (by dst) + edge_attr permutation
    hist_kernel<<<EB, 256>>>(ei);
    scan_kernel<<<1, 1024>>>();
    scatter_kernel<<<EB, 256>>>(ei, ea);

    // layer 0 (CIN = 32)
    copyu_kernel<<<CB, 256>>>(x);
    gather_kernel<cDIN><<<GB, 256>>>(x, 0, l0ew, l0eb);
    node_kernel<cDIN><<<NB, 256, SM32>>>(l0w1, l0b1, l0w2, l0b2);
    norm_kernel<<<MB, 256>>>(bng, bnb, batch, 0);

    // layers 1..3 (CIN = 64)
    for (int i = 0; i < 3; i++) {
        int last = (i == 2) ? 1 : 0;
        gather_kernel<cH><<<GB, 256>>>(nullptr, 1,
                                       ewA + (size_t)i * cH * cDE, ebA + (size_t)i * cH);
        node_kernel<cH><<<NB, 256, SM64>>>(w1A + (size_t)i * cH * cH, b1A + (size_t)i * cH,
                                           w2A + (size_t)i * cH * cH, b2A + (size_t)i * cH);
        norm_kernel<<<MB, 256>>>(bng + (size_t)(i + 1) * cH,
                                 bnb + (size_t)(i + 1) * cH, batch, last);
    }

    head_kernel<<<cG, 128>>>(hw1, hb1, hw2, hb2, out);
}

// round 13
// speedup vs baseline: 2.2638x; 1.1202x over previous
#include <cuda_runtime.h>
#include <cstdint>

#define DEV_INLINE __device__ __forceinline__

constexpr int cN   = 100000;   // nodes
constexpr int cE   = 1600000;  // edges
constexpr int cDIN = 32;       // node in channels
constexpr int cDE  = 16;       // edge feature dim
constexpr int cH   = 64;       // hidden
constexpr int cMH  = 128;      // mlp hidden
constexpr int cOUT = 10;       // out channels
constexpr int cG   = 128;      // graphs
constexpr int EPW  = 64;       // edges per warp (2 pipelined chunks of 32)

typedef unsigned long long ull;

// ---------------- scratch (device globals; no allocation allowed) ----------
__device__ __align__(16) float g_u[cN * cH];       // x + agg (node MLP input)
__device__ __align__(16) float g_h[cN * cH];       // node MLP output (pre-BN)
__device__ __align__(16) float g_x[cN * cH];       // post-BN activations
__device__ __align__(16) float g_ea_perm[(size_t)cE * cDE];  // ea in CSR order
__device__ __align__(16) int   g_src[cE];          // src in CSR order
__device__ __align__(16) int   g_dst[cE];          // dst in CSR order (sorted)
__device__ __align__(16) int   g_deg[cN];          // zeroed by scan (self-restoring)
__device__ __align__(16) int   g_woff[cN];
__device__ __align__(16) int   g_rowptr[cN + 1];
__device__ __align__(16) float g_sum[cH];
__device__ __align__(16) float g_sumsq[cH];
__device__ __align__(16) float g_pool[cG * cH];
__device__ __align__(16) int   g_cnt[cG];

DEV_INLINE void red_add_v4(float* p, float a, float b, float c, float d) {
    asm volatile("red.global.add.v4.f32 [%0], {%1,%2,%3,%4};"
                 :: "l"(p), "f"(a), "f"(b), "f"(c), "f"(d) : "memory");
}
DEV_INLINE void red_add_v2(float* p, float a, float b) {
    asm volatile("red.global.add.v2.f32 [%0], {%1,%2};"
                 :: "l"(p), "f"(a), "f"(b) : "memory");
}
DEV_INLINE void red_add_1(float* p, float a) {
    asm volatile("red.global.add.f32 [%0], %1;" :: "l"(p), "f"(a) : "memory");
}
DEV_INLINE ull ffma2(ull a, ull b, ull c) {
    ull d;
    asm("fma.rn.f32x2 %0, %1, %2, %3;" : "=l"(d) : "l"(a), "l"(b), "l"(c));
    return d;
}
DEV_INLINE ull pack2(float lo, float hi) {
    ull v;
    asm("mov.b64 %0, {%1, %2};" : "=l"(v) : "f"(lo), "f"(hi));
    return v;
}
DEV_INLINE float2 unpack2(ull v) {
    float2 f;
    asm("mov.b64 {%0, %1}, %2;" : "=f"(f.x), "=f"(f.y) : "l"(v));
    return f;
}
DEV_INLINE uint32_t s2u(const void* p) {
    uint32_t a;
    asm("{ .reg .u64 t; cvta.to.shared.u64 t, %1; cvt.u32.u64 %0, t; }"
        : "=r"(a) : "l"(p));
    return a;
}
DEV_INLINE void cp16(uint32_t smem, const void* g) {
    asm volatile("cp.async.ca.shared.global [%0], [%1], 16;"
                 :: "r"(smem), "l"(g) : "memory");
}
#define CP_COMMIT() asm volatile("cp.async.commit_group;" ::: "memory")
#define CP_WAIT1()  asm volatile("cp.async.wait_group 1;" ::: "memory")
#define CP_WAIT0()  asm volatile("cp.async.wait_group 0;" ::: "memory")

// ---------------- CSR build -------------------------------------------------
// hist also zeroes pool/cnt and seeds g_u = x (layer-0 input).
// g_deg is zero at load and re-zeroed by scan each call: deterministic.
__global__ void __launch_bounds__(256) hist_kernel(
    const int* __restrict__ ei, const float* __restrict__ x)
{
    int i = blockIdx.x * 256 + threadIdx.x;
    if (i < cG * cH) g_pool[i] = 0.f;
    if (i < cG) g_cnt[i] = 0;
    if (i < cN * cDIN / 4) ((float4*)g_u)[i] = ((const float4*)x)[i];
    if (i < cE) atomicAdd(&g_deg[ei[cE + i]], 1);
}

__global__ void __launch_bounds__(1024) scan_kernel() {
    const int TP = (cN + 1023) / 1024;  // 98
    int t = threadIdx.x;
    int s0 = t * TP, s1 = min(s0 + TP, cN);
    int ls = 0;
    for (int i = s0; i < s1; i++) ls += g_deg[i];
    __shared__ int ps[1024];
    ps[t] = ls;
    __syncthreads();
    for (int off = 1; off < 1024; off <<= 1) {
        int v = (t >= off) ? ps[t - off] : 0;
        __syncthreads();
        ps[t] += v;
        __syncthreads();
    }
    int run = ps[t] - ls;
    for (int i = s0; i < s1; i++) {
        int d = g_deg[i];
        g_deg[i] = 0;          // restore for next call's hist
        g_rowptr[i] = run;
        g_woff[i]   = run;
        run += d;
    }
    if (t == 0) g_rowptr[cN] = cE;
}

// scatter + permute edge_attr into CSR (dst-sorted) order, fused
__global__ void __launch_bounds__(256) scatter_kernel(
    const int* __restrict__ ei, const float* __restrict__ ea)
{
    int e = blockIdx.x * 256 + threadIdx.x;
    if (e >= cE) return;
    int s = ei[e], d = ei[cE + e];
    int pos = atomicAdd(&g_woff[d], 1);
    g_src[pos] = s;
    g_dst[pos] = d;
    const float4* sp = (const float4*)(ea + (size_t)e * cDE);
    float4 a = sp[0], b = sp[1], c = sp[2], dd = sp[3];
    float4* dp = (float4*)(g_ea_perm + (size_t)pos * cDE);
    dp[0] = a; dp[1] = b; dp[2] = c; dp[3] = dd;
}

// ---------------- segmented gather: g_u[d] += relu(x[src]+ea@W^T+b) --------
// Warp owns 64 consecutive CSR edges (two 32-edge chunks, double-buffered
// cp.async ea staging). Lanes = channels. src/dst live in registers,
// broadcast per edge via shfl. Flush via red.add at segment boundaries.
template <int C>
__global__ void __launch_bounds__(256) gather_kernel(
    const float* __restrict__ xin, int use_internal,
    const float* __restrict__ ew, const float* __restrict__ eb)
{
    constexpr int CPT = C / 32;   // 1 (layer0) or 2
    constexpr int KP  = cDE / 2;  // 8 k-pairs

    __shared__ __align__(16) float ea_s[8][2][32 * cDE];   // 32KB

    const float* x = use_internal ? g_x : xin;
    int t = threadIdx.x;
    int lane = t & 31;
    int w = t >> 5;

    if (blockIdx.x == 0 && t < cH) { g_sum[t] = 0.f; g_sumsq[t] = 0.f; }

    int c0 = lane * CPT;
    ull wreg[CPT][KP];
    float ebr[CPT];
    #pragma unroll
    for (int c = 0; c < CPT; c++) {
        #pragma unroll
        for (int j = 0; j < KP; j++)
            wreg[c][j] = *(const ull*)&ew[(c0 + c) * cDE + 2 * j];
        ebr[c] = eb[c0 + c];
    }

    int base = (blockIdx.x * 8 + w) * EPW;   // grid exact: base+EPW <= cE

    // ids for both chunks (coalesced, register-resident)
    int sc0 = g_src[base + lane],      sc1 = g_src[base + 32 + lane];
    int dc0 = g_dst[base + lane],      dc1 = g_dst[base + 32 + lane];

    // stage both ea chunks via cp.async (2KB each)
    uint32_t sb0 = s2u(&ea_s[w][0][0]);
    uint32_t sb1 = s2u(&ea_s[w][1][0]);
    const char* gp = (const char*)(g_ea_perm) + (size_t)base * (cDE * 4);
    #pragma unroll
    for (int i = 0; i < 4; i++)
        cp16(sb0 + i * 512 + lane * 16, gp + i * 512 + lane * 16);
    CP_COMMIT();
    #pragma unroll
    for (int i = 0; i < 4; i++)
        cp16(sb1 + i * 512 + lane * 16, gp + 2048 + i * 512 + lane * 16);
    CP_COMMIT();

    float acc0 = 0.f, acc1 = 0.f;
    int cur = __shfl_sync(0xffffffffu, dc0, 0);

    auto process = [&](const float* eabuf, int sc, int dc) {
        for (int g = 0; g < 32; g += 4) {
            int ss[4], dd[4];
            #pragma unroll
            for (int r = 0; r < 4; r++) {
                ss[r] = __shfl_sync(0xffffffffu, sc, g + r);
                dd[r] = __shfl_sync(0xffffffffu, dc, g + r);
            }
            float xa[4], xb[4];
            if (CPT == 2) {
                #pragma unroll
                for (int r = 0; r < 4; r++) {
                    float2 xx = *(const float2*)(x + (size_t)ss[r] * C + c0);
                    xa[r] = xx.x; xb[r] = xx.y;
                }
            } else {
                #pragma unroll
                for (int r = 0; r < 4; r++) xa[r] = x[(size_t)ss[r] * C + c0];
            }
            #pragma unroll
            for (int r = 0; r < 4; r++) {
                if (dd[r] != cur) {   // warp-uniform branch
                    if (CPT == 2) red_add_v2(&g_u[(size_t)cur * C + c0], acc0, acc1);
                    else          red_add_1(&g_u[(size_t)cur * C + c0], acc0);
                    acc0 = 0.f; acc1 = 0.f;
                    cur = dd[r];
                }
                const ulonglong2* eap = (const ulonglong2*)(eabuf + (g + r) * cDE);
                ulonglong2 p0 = eap[0], p1 = eap[1], p2 = eap[2], p3 = eap[3];
                if (CPT == 2) {
                    ull d0 = pack2(ebr[0], 0.f), d1 = pack2(ebr[1], 0.f);
                    d0 = ffma2(wreg[0][0], p0.x, d0); d1 = ffma2(wreg[1][0], p0.x, d1);
                    d0 = ffma2(wreg[0][1], p0.y, d0); d1 = ffma2(wreg[1][1], p0.y, d1);
                    d0 = ffma2(wreg[0][2], p1.x, d0); d1 = ffma2(wreg[1][2], p1.x, d1);
                    d0 = ffma2(wreg[0][3], p1.y, d0); d1 = ffma2(wreg[1][3], p1.y, d1);
                    d0 = ffma2(wreg[0][4], p2.x, d0); d1 = ffma2(wreg[1][4], p2.x, d1);
                    d0 = ffma2(wreg[0][5], p2.y, d0); d1 = ffma2(wreg[1][5], p2.y, d1);
                    d0 = ffma2(wreg[0][6], p3.x, d0); d1 = ffma2(wreg[1][6], p3.x, d1);
                    d0 = ffma2(wreg[0][7], p3.y, d0); d1 = ffma2(wreg[1][7], p3.y, d1);
                    float2 pa = unpack2(d0), pb = unpack2(d1);
                    acc0 += fmaxf(xa[r] + pa.x + pa.y, 0.f);
                    acc1 += fmaxf(xb[r] + pb.x + pb.y, 0.f);
                } else {
                    ull d0 = pack2(ebr[0], 0.f);
                    d0 = ffma2(wreg[0][0], p0.x, d0);
                    d0 = ffma2(wreg[0][1], p0.y, d0);
                    d0 = ffma2(wreg[0][2], p1.x, d0);
                    d0 = ffma2(wreg[0][3], p1.y, d0);
                    d0 = ffma2(wreg[0][4], p2.x, d0);
                    d0 = ffma2(wreg[0][5], p2.y, d0);
                    d0 = ffma2(wreg[0][6], p3.x, d0);
                    d0 = ffma2(wreg[0][7], p3.y, d0);
                    float2 pa = unpack2(d0);
                    acc0 += fmaxf(xa[r] + pa.x + pa.y, 0.f);
                }
            }
        }
    };

    CP_WAIT1();
    __syncwarp();
    process(&ea_s[w][0][0], sc0, dc0);
    CP_WAIT0();
    __syncwarp();
    process(&ea_s[w][1][0], sc1, dc1);

    if (CPT == 2) red_add_v2(&g_u[(size_t)cur * C + c0], acc0, acc1);
    else          red_add_1(&g_u[(size_t)cur * C + c0], acc0);
}

// ---------------- node update: h2 = relu(relu(u W1^T + b1) W2^T + b2) ------
template <int CIN>
__global__ void __launch_bounds__(256, 2) node_kernel(
    const float* __restrict__ w1, const float* __restrict__ b1,
    const float* __restrict__ w2, const float* __restrict__ b2)
{
    constexpr int KP1 = CIN / 2;   // 16 or 32
    constexpr int US  = KP1 + 1;
    constexpr int KP2 = cH / 2;    // 32
    constexpr int HS  = KP2 + 1;   // 33
    constexpr int WS  = KP2 + 1;

    extern __shared__ __align__(16) ull dyn[];
    ull* us2 = dyn;                    // [128 * US]
    ull* ws2 = us2 + 128 * US;         // [64 * WS]
    ull* hs2 = ws2 + 64 * WS;          // [128 * HS]
    float* hsf = (float*)hs2;

    int t = threadIdx.x;
    int lane = t & 31;
    int w = t >> 5;
    int n0 = blockIdx.x * 128;

    for (int i = t; i < 128 * KP1; i += 256) {
        int n = i / KP1, j = i % KP1;
        us2[n * US + j] = (n0 + n < cN)
            ? *(const ull*)&g_u[(size_t)(n0 + n) * CIN + 2 * j] : 0ull;
    }
    for (int i = t; i < cH * KP1; i += 256) {
        int r = i / KP1, j = i % KP1;
        ws2[r * WS + j] = ((const ull*)w1)[i];
    }
    __syncthreads();

    // ---- GEMM 1 ----
    ull acc2[4][8];
    #pragma unroll
    for (int j = 0; j < 8; j++) {
        ull b = pack2(b1[w * 8 + j], 0.f);
        #pragma unroll
        for (int i = 0; i < 4; i++) acc2[i][j] = b;
    }
    for (int kp = 0; kp < KP1; kp++) {
        ull wt[8], uv[4];
        #pragma unroll
        for (int j = 0; j < 8; j++) wt[j] = ws2[(w * 8 + j) * WS + kp];
        #pragma unroll
        for (int i = 0; i < 4; i++) uv[i] = us2[(lane + 32 * i) * US + kp];
        #pragma unroll
        for (int i = 0; i < 4; i++)
            #pragma unroll
            for (int j = 0; j < 8; j++)
                acc2[i][j] = ffma2(wt[j], uv[i], acc2[i][j]);
    }
    #pragma unroll
    for (int i = 0; i < 4; i++) {
        int n = lane + 32 * i;
        #pragma unroll
        for (int j = 0; j < 8; j += 2) {
            float2 pa = unpack2(acc2[i][j]);
            float2 pb = unpack2(acc2[i][j + 1]);
            ull pk = pack2(fmaxf(pa.x + pa.y, 0.f), fmaxf(pb.x + pb.y, 0.f));
            *(ull*)&hsf[n * (2 * HS) + w * 8 + j] = pk;
        }
    }
    __syncthreads();

    for (int i = t; i < cH * KP2; i += 256) {
        int r = i / KP2, j = i % KP2;
        ws2[r * WS + j] = ((const ull*)w2)[i];
    }
    __syncthreads();

    // ---- GEMM 2 ----
    #pragma unroll
    for (int j = 0; j < 8; j++) {
        ull b = pack2(b2[w * 8 + j], 0.f);
        #pragma unroll
        for (int i = 0; i < 4; i++) acc2[i][j] = b;
    }
    for (int kp = 0; kp < KP2; kp++) {
        ull wt[8], uv[4];
        #pragma unroll
        for (int j = 0; j < 8; j++) wt[j] = ws2[(w * 8 + j) * WS + kp];
        #pragma unroll
        for (int i = 0; i < 4; i++) uv[i] = hs2[(lane + 32 * i) * HS + kp];
        #pragma unroll
        for (int i = 0; i < 4; i++)
            #pragma unroll
            for (int j = 0; j < 8; j++)
                acc2[i][j] = ffma2(wt[j], uv[i], acc2[i][j]);
    }

    float v[4][8];
    float s[8], q[8];
    #pragma unroll
    for (int j = 0; j < 8; j++) { s[j] = 0.f; q[j] = 0.f; }
    #pragma unroll
    for (int i = 0; i < 4; i++) {
        bool valid = (n0 + lane + 32 * i) < cN;
        #pragma unroll
        for (int j = 0; j < 8; j++) {
            float2 p = unpack2(acc2[i][j]);
            float vv = valid ? fmaxf(p.x + p.y, 0.f) : 0.f;
            v[i][j] = vv;
            s[j] += vv; q[j] += vv * vv;
        }
    }
    #pragma unroll
    for (int j = 0; j < 8; j++) {
        #pragma unroll
        for (int off = 16; off > 0; off >>= 1) {
            s[j] += __shfl_xor_sync(0xffffffffu, s[j], off);
            q[j] += __shfl_xor_sync(0xffffffffu, q[j], off);
        }
    }
    if (lane == 0) {
        #pragma unroll
        for (int j = 0; j < 8; j++) {
            atomicAdd(&g_sum[w * 8 + j], s[j]);
            atomicAdd(&g_sumsq[w * 8 + j], q[j]);
        }
    }

    __syncthreads();
    #pragma unroll
    for (int i = 0; i < 4; i++) {
        int n = lane + 32 * i;
        #pragma unroll
        for (int j = 0; j < 8; j += 2) {
            ull pk = pack2(v[i][j], v[i][j + 1]);
            *(ull*)&hsf[n * (2 * HS) + w * 8 + j] = pk;
        }
    }
    __syncthreads();
    for (int i = t; i < 128 * cH / 2; i += 256) {
        int n = i / KP2, j = i % KP2;
        if (n0 + n < cN)
            *(ull*)&g_h[(size_t)(n0 + n) * cH + 2 * j] = *(ull*)&hsf[n * (2 * HS) + 2 * j];
    }
}

// ---------------- BN normalize (+relu); writes g_x and (if !last) g_u ------
__global__ void __launch_bounds__(256) norm_kernel(
    const float* __restrict__ gamma, const float* __restrict__ beta,
    const int* __restrict__ batch, int last)
{
    int idx = blockIdx.x * 256 + threadIdx.x;
    if (idx >= cN * 16) return;
    int node = idx >> 4;
    int c0 = (idx & 15) * 4;
    float4 h = ((const float4*)g_h)[idx];
    float v[4] = {h.x, h.y, h.z, h.w};
    #pragma unroll
    for (int j = 0; j < 4; j++) {
        int c = c0 + j;
        float mu  = g_sum[c]   * (1.f / cN);
        float var = g_sumsq[c] * (1.f / cN) - mu * mu;
        float sc  = rsqrtf(var + 1e-5f) * gamma[c];
        v[j] = fmaxf((v[j] - mu) * sc + beta[c], 0.f);
    }
    float4 vv = make_float4(v[0], v[1], v[2], v[3]);
    ((float4*)g_x)[idx] = vv;
    if (!last) {
        ((float4*)g_u)[idx] = vv;     // seed u = x for next layer's gather
    } else {
        int b = batch[node];
        red_add_v4(&g_pool[b * cH + c0], v[0], v[1], v[2], v[3]);
        if (c0 == 0) atomicAdd(&g_cnt[b], 1);
    }
}

// ---------------- pooled mean + MLP head -----------------------------------
__global__ void __launch_bounds__(128) head_kernel(
    const float* __restrict__ hw1, const float* __restrict__ hb1,
    const float* __restrict__ hw2, const float* __restrict__ hb2,
    float* __restrict__ out)
{
    __shared__ float p[cH], z[cMH];
    int g = blockIdx.x, t = threadIdx.x;
    if (t < cH) p[t] = g_pool[g * cH + t] / fmaxf((float)g_cnt[g], 1.f);
    __syncthreads();
    float acc = hb1[t];
    for (int c = 0; c < cH; c++) acc += p[c] * hw1[t * cH + c];
    z[t] = fmaxf(acc, 0.f);
    __syncthreads();
    if (t < cOUT) {
        float a = hb2[t];
        for (int m = 0; m < cMH; m++) a += z[m] * hw2[t * cMH + m];
        out[g * cOUT + t] = a;
    }
}

// ---------------- launch ----------------------------------------------------
extern "C" void kernel_launch(void* const* d_in, const int* in_sizes, int n_in,
                              void* d_out, int out_size)
{
    const float* x    = (const float*)d_in[0];
    const int*   ei   = (const int*)  d_in[1];
    const float* ea   = (const float*)d_in[2];
    const int*   batch= (const int*)  d_in[3];
    const float* l0ew = (const float*)d_in[4];
    const float* l0eb = (const float*)d_in[5];
    const float* l0w1 = (const float*)d_in[6];
    const float* l0b1 = (const float*)d_in[7];
    const float* l0w2 = (const float*)d_in[8];
    const float* l0b2 = (const float*)d_in[9];
    const float* ewA  = (const float*)d_in[10];  // [3, H, DE]
    const float* ebA  = (const float*)d_in[11];  // [3, H]
    const float* w1A  = (const float*)d_in[12];  // [3, H, H]
    const float* b1A  = (const float*)d_in[13];
    const float* w2A  = (const float*)d_in[14];
    const float* b2A  = (const float*)d_in[15];
    const float* bng  = (const float*)d_in[16];  // [4, H]
    const float* bnb  = (const float*)d_in[17];
    const float* hw1  = (const float*)d_in[18];
    const float* hb1  = (const float*)d_in[19];
    const float* hw2  = (const float*)d_in[20];
    const float* hb2  = (const float*)d_in[21];
    float* out = (float*)d_out;

    const int EB = (cE + 255) / 256;       // 6250
    const int GB = cE / (8 * EPW);         // 3125 (exact: 1.6M / 512)
    const int NB = (cN + 127) / 128;       // 782
    const int MB = cN * 16 / 256;          // 6250

    const int SM32 = (128 * (cDIN / 2 + 1) + cH * 33 + 128 * 33) * 8;
    const int SM64 = (128 * (cH   / 2 + 1) + cH * 33 + 128 * 33) * 8;
    cudaFuncSetAttribute(node_kernel<cDIN>,
                         cudaFuncAttributeMaxDynamicSharedMemorySize, SM32);
    cudaFuncSetAttribute(node_kernel<cH>,
                         cudaFuncAttributeMaxDynamicSharedMemorySize, SM64);

    // CSR build (by dst) + edge_attr permutation + g_u seed
    hist_kernel<<<EB, 256>>>(ei, x);
    scan_kernel<<<1, 1024>>>();
    scatter_kernel<<<EB, 256>>>(ei, ea);

    // layer 0 (CIN = 32) — gather is the 4th launch (ncu capture target)
    gather_kernel<cDIN><<<GB, 256>>>(x, 0, l0ew, l0eb);
    node_kernel<cDIN><<<NB, 256, SM32>>>(l0w1, l0b1, l0w2, l0b2);
    norm_kernel<<<MB, 256>>>(bng, bnb, batch, 0);

    // layers 1..3 (CIN = 64)
    for (int i = 0; i < 3; i++) {
        int last = (i == 2) ? 1 : 0;
        gather_kernel<cH><<<GB, 256>>>(nullptr, 1,
                                       ewA + (size_t)i * cH * cDE, ebA + (size_t)i * cH);
        node_kernel<cH><<<NB, 256, SM64>>>(w1A + (size_t)i * cH * cH, b1A + (size_t)i * cH,
                                           w2A + (size_t)i * cH * cH, b2A + (size_t)i * cH);
        norm_kernel<<<MB, 256>>>(bng + (size_t)(i + 1) * cH,
                                 bnb + (size_t)(i + 1) * cH, batch, last);
    }

    head_kernel<<<cG, 128>>>(hw1, hb1, hw2, hb2, out);
}